// round 10
// baseline (speedup 1.0000x reference)
#include <cuda_runtime.h>
#include <cuda_bf16.h>
#include <math.h>

#define N_NODES 50000
#define D_IN    128
#define D_HID   128
#define D_OUT   64

// ---------------- device scratch (~19.8 MB) ----------------
__device__ float g_dinv[N_NODES];            // deg^{-1/2}
__device__ int   g_cnt [N_NODES];            // in-degree (edges only)
__device__ int   g_cur [N_NODES];            // scan result -> fill cursor -> end ptr
__device__ int2  g_edge[800000];             // CSR payload: {src, norm bits}
__device__ float g_hi  [N_NODES * 64];       // hi half of layer-1 agg / Q

__device__ __forceinline__ int clamp_node(int v) {
    return min(max(v, 0), N_NODES - 1);
}

// ---------------- CSR build ----------------
__global__ void k_zero_cnt() {
    int i = blockIdx.x * blockDim.x + threadIdx.x;
    if (i < N_NODES) g_cnt[i] = 0;
}

__global__ void k_count(const int* __restrict__ dst, int E) {
    int e = blockIdx.x * blockDim.x + threadIdx.x;
    if (e < E) atomicAdd(&g_cnt[clamp_node(__ldg(dst + e))], 1);
}

__global__ void k_dinv() {
    int i = blockIdx.x * blockDim.x + threadIdx.x;
    if (i < N_NODES) g_dinv[i] = rsqrtf(1.0f + (float)g_cnt[i]);   // +1 self loop
}

// single-block exclusive scan of g_cnt -> g_cur (1024 threads, Hillis-Steele)
__global__ void k_scan() {
    __shared__ int s[1024];
    __shared__ int carry;
    const int tid = threadIdx.x;
    if (tid == 0) carry = 0;
    __syncthreads();
    for (int base = 0; base < N_NODES; base += 1024) {
        int i = base + tid;
        int v = (i < N_NODES) ? g_cnt[i] : 0;
        s[tid] = v;
        __syncthreads();
        #pragma unroll
        for (int o = 1; o < 1024; o <<= 1) {
            int t = (tid >= o) ? s[tid - o] : 0;
            __syncthreads();
            s[tid] += t;
            __syncthreads();
        }
        if (i < N_NODES) g_cur[i] = carry + s[tid] - v;   // exclusive
        __syncthreads();
        if (tid == 0) carry += s[1023];
        __syncthreads();
    }
}

// bucket fill: g_edge[pos] = {src, dinv[s]*dinv[d]}; g_cur advances to end
__global__ void k_fill(const int* __restrict__ src, const int* __restrict__ dst, int E) {
    int e = blockIdx.x * blockDim.x + threadIdx.x;
    if (e >= E) return;
    int s = clamp_node(__ldg(src + e));
    int d = clamp_node(__ldg(dst + e));
    float nrm = g_dinv[s] * g_dinv[d];
    int pos = atomicAdd(&g_cur[d], 1);
    g_edge[pos] = make_int2(s, __float_as_int(nrm));
}

// ---------------- layer-1 gather: AGGX = Â·x (split lo=d_out / g_hi) -------
// one warp per dst node; lane owns 4 of 128 columns; next-edge prefetch
__global__ __launch_bounds__(256) void k_gather1(const float* __restrict__ x,
                                                 float* __restrict__ lo) {
    int node = blockIdx.x * 8 + (threadIdx.x >> 5);
    int lane = threadIdx.x & 31;
    if (node >= N_NODES) return;
    float di = g_dinv[node];
    float4 acc = *(const float4*)(x + (size_t)node * 128 + lane * 4);
    float nn = di * di;
    acc.x *= nn; acc.y *= nn; acc.z *= nn; acc.w *= nn;

    int end = g_cur[node];            // after fill: end of bucket
    int beg = end - g_cnt[node];

    if (beg < end) {
        int2 e = __ldg(&g_edge[beg]);
        float4 v = *(const float4*)(x + (size_t)e.x * 128 + lane * 4);
        for (int j = beg; j < end; j++) {
            float nrm = __int_as_float(e.y);
            float4 cv = v;
            if (j + 1 < end) {                     // prefetch next edge
                e = __ldg(&g_edge[j + 1]);
                v = *(const float4*)(x + (size_t)e.x * 128 + lane * 4);
            }
            acc.x = fmaf(cv.x, nrm, acc.x);
            acc.y = fmaf(cv.y, nrm, acc.y);
            acc.z = fmaf(cv.z, nrm, acc.z);
            acc.w = fmaf(cv.w, nrm, acc.w);
        }
    }
    float* p = (lane < 16) ? (lo + (size_t)node * 64 + lane * 4)
                           : (g_hi + (size_t)node * 64 + (lane - 16) * 4);
    *(float4*)p = acc;
}

// ---------------- P = relu(AGGX @ W1 + b1), in place over split ------------
__global__ __launch_bounds__(256) void k_gemm1(const float* __restrict__ W1,
                                               const float* __restrict__ b1,
                                               float* __restrict__ lo) {
    __shared__ float sX[32][128];      // 16 KB
    __shared__ float sW[128 * 64];     // 32 KB
    const int tid = threadIdx.x;
    const int row0 = blockIdx.x * 32;

    for (int i = tid; i < 32 * 32; i += 256) {
        int r = i >> 5, c = i & 31;
        int row = row0 + r;
        float4 v = make_float4(0.f, 0.f, 0.f, 0.f);
        if (row < N_NODES)
            v = (c < 16) ? *(const float4*)(lo + (size_t)row * 64 + c * 4)
                         : *(const float4*)(g_hi + (size_t)row * 64 + (c - 16) * 4);
        *(float4*)(&sX[r][c * 4]) = v;
    }

    const int warp = tid >> 5, lane = tid & 31;
    float accA[4][2] = {}, accB[4][2] = {};

    #pragma unroll
    for (int half = 0; half < 2; half++) {
        __syncthreads();
        for (int i = tid; i < 128 * 16; i += 256) {    // W half [128 x 64]
            int k = i >> 4, c4 = i & 15;
            ((float4*)sW)[i] = *(const float4*)(W1 + (size_t)k * 128 + half * 64 + c4 * 4);
        }
        __syncthreads();
        #pragma unroll 4
        for (int k = 0; k < 128; k++) {
            float2 wv = *(const float2*)(sW + k * 64 + lane * 2);
            #pragma unroll
            for (int r = 0; r < 4; r++) {
                float xv = sX[warp * 4 + r][k];
                if (half == 0) {
                    accA[r][0] = fmaf(xv, wv.x, accA[r][0]);
                    accA[r][1] = fmaf(xv, wv.y, accA[r][1]);
                } else {
                    accB[r][0] = fmaf(xv, wv.x, accB[r][0]);
                    accB[r][1] = fmaf(xv, wv.y, accB[r][1]);
                }
            }
        }
    }

    float2 bA = *(const float2*)(b1 + lane * 2);
    float2 bB = *(const float2*)(b1 + 64 + lane * 2);
    #pragma unroll
    for (int r = 0; r < 4; r++) {
        int row = row0 + warp * 4 + r;
        if (row < N_NODES) {
            float2 oA = make_float2(fmaxf(accA[r][0] + bA.x, 0.f),
                                    fmaxf(accA[r][1] + bA.y, 0.f));
            float2 oB = make_float2(fmaxf(accB[r][0] + bB.x, 0.f),
                                    fmaxf(accB[r][1] + bB.y, 0.f));
            *(float2*)(lo   + (size_t)row * 64 + lane * 2) = oA;
            *(float2*)(g_hi + (size_t)row * 64 + lane * 2) = oB;
        }
    }
}

// ---------------- Q = P @ W2, in place into g_hi ---------------------------
__global__ __launch_bounds__(256) void k_gemm2(const float* __restrict__ W2,
                                               const float* __restrict__ lo) {
    __shared__ float sX[32][128];      // 16 KB
    __shared__ float sW[128 * 64];     // 32 KB
    const int tid = threadIdx.x;
    const int row0 = blockIdx.x * 32;

    for (int i = tid; i < 32 * 32; i += 256) {
        int r = i >> 5, c = i & 31;
        int row = row0 + r;
        float4 v = make_float4(0.f, 0.f, 0.f, 0.f);
        if (row < N_NODES)
            v = (c < 16) ? *(const float4*)(lo + (size_t)row * 64 + c * 4)
                         : *(const float4*)(g_hi + (size_t)row * 64 + (c - 16) * 4);
        *(float4*)(&sX[r][c * 4]) = v;
    }
    for (int i = tid; i < 128 * 16; i += 256) {        // W2 [128 x 64]
        int k = i >> 4, c4 = i & 15;
        ((float4*)sW)[i] = *(const float4*)(W2 + (size_t)k * 64 + c4 * 4);
    }
    __syncthreads();

    const int warp = tid >> 5, lane = tid & 31;
    float acc[4][2] = {};
    #pragma unroll 4
    for (int k = 0; k < 128; k++) {
        float2 wv = *(const float2*)(sW + k * 64 + lane * 2);
        #pragma unroll
        for (int r = 0; r < 4; r++) {
            float xv = sX[warp * 4 + r][k];
            acc[r][0] = fmaf(xv, wv.x, acc[r][0]);
            acc[r][1] = fmaf(xv, wv.y, acc[r][1]);
        }
    }
    #pragma unroll
    for (int r = 0; r < 4; r++) {
        int row = row0 + warp * 4 + r;
        if (row < N_NODES)
            *(float2*)(g_hi + (size_t)row * 64 + lane * 2)
                = make_float2(acc[r][0], acc[r][1]);
    }
}

// ---------------- layer-2 gather + bias + log_softmax, fused ---------------
// one warp per dst node; lane owns 2 of 64 columns; next-edge prefetch
__global__ __launch_bounds__(256) void k_gather2_lsm(const float* __restrict__ b2,
                                                     float* __restrict__ out) {
    int node = blockIdx.x * 8 + (threadIdx.x >> 5);
    int lane = threadIdx.x & 31;
    if (node >= N_NODES) return;
    float di = g_dinv[node];
    float2 acc = *(const float2*)(g_hi + (size_t)node * 64 + lane * 2);
    float nn = di * di;
    acc.x *= nn; acc.y *= nn;

    int end = g_cur[node];
    int beg = end - g_cnt[node];

    if (beg < end) {
        int2 e = __ldg(&g_edge[beg]);
        float2 v = *(const float2*)(g_hi + (size_t)e.x * 64 + lane * 2);
        for (int j = beg; j < end; j++) {
            float nrm = __int_as_float(e.y);
            float2 cv = v;
            if (j + 1 < end) {                     // prefetch next edge
                e = __ldg(&g_edge[j + 1]);
                v = *(const float2*)(g_hi + (size_t)e.x * 64 + lane * 2);
            }
            acc.x = fmaf(cv.x, nrm, acc.x);
            acc.y = fmaf(cv.y, nrm, acc.y);
        }
    }

    float2 bb = *(const float2*)(b2 + lane * 2);
    acc.x += bb.x; acc.y += bb.y;
    float m = fmaxf(acc.x, acc.y);
    #pragma unroll
    for (int o = 16; o; o >>= 1) m = fmaxf(m, __shfl_xor_sync(0xFFFFFFFFu, m, o));
    float s = __expf(acc.x - m) + __expf(acc.y - m);
    #pragma unroll
    for (int o = 16; o; o >>= 1) s += __shfl_xor_sync(0xFFFFFFFFu, s, o);
    float l = m + __logf(s);
    *(float2*)(out + (size_t)node * 64 + lane * 2)
        = make_float2(acc.x - l, acc.y - l);
}

// ---------------- launch ----------------
extern "C" void kernel_launch(void* const* d_in, const int* in_sizes, int n_in,
                              void* d_out, int out_size) {
    const float* x  = (const float*)d_in[0];
    const int*   ei = (const int*)d_in[1];        // int64 ref -> int32 delivered
    const float* W1 = (const float*)d_in[2];
    const float* b1 = (const float*)d_in[3];
    const float* W2 = (const float*)d_in[4];
    const float* b2 = (const float*)d_in[5];
    float* out = (float*)d_out;

    const int E = in_sizes[1] / 2;
    const int* src = ei;
    const int* dst = ei + E;

    const int TB = 256;
    const int nbN = (N_NODES + TB - 1) / TB;
    const int nbE = (E + TB - 1) / TB;
    const int nbW = (N_NODES + 7) / 8;            // warp-per-node kernels

    // 1) CSR build: count, dinv, scan, fill
    k_zero_cnt<<<nbN, TB>>>();
    k_count   <<<nbE, TB>>>(dst, E);
    k_dinv    <<<nbN, TB>>>();
    k_scan    <<<1, 1024>>>();
    k_fill    <<<nbE, TB>>>(src, dst, E);

    // 2) AGGX = Â·x   (gather; split lo=d_out cols 0..63, g_hi cols 64..127)
    k_gather1<<<nbW, TB>>>(x, out);

    // 3) P = relu(AGGX @ W1 + b1)   in place over split storage
    k_gemm1<<<(N_NODES + 31) / 32, TB>>>(W1, b1, out);

    // 4) Q = P @ W2   -> g_hi
    k_gemm2<<<(N_NODES + 31) / 32, TB>>>(W2, out);

    // 5+6) d_out = log_softmax(Â·Q + b2)   (fused gather + bias + softmax)
    k_gather2_lsm<<<nbW, TB>>>(b2, out);
}

// round 12
// speedup vs baseline: 1.3396x; 1.3396x over previous
#include <cuda_runtime.h>
#include <cuda_bf16.h>
#include <math.h>

#define N_NODES 50000
#define D_IN    128
#define D_HID   128
#define D_OUT   64
#define SCAN_NB ((N_NODES + 1023) / 1024)    // 49 blocks

// ---------------- device scratch (~19.8 MB) ----------------
__device__ float g_dinv[N_NODES];            // deg^{-1/2}
__device__ int   g_cnt [N_NODES];            // in-degree (edges only)
__device__ int   g_cur [N_NODES];            // scan result -> fill cursor -> end ptr
__device__ int   g_bsum[64];                 // per-block scan totals
__device__ int2  g_edge[800000];             // CSR payload: {src, norm bits}
__device__ float g_hi  [N_NODES * 64];       // hi half of layer-1 agg / Q

__device__ __forceinline__ int clamp_node(int v) {
    return min(max(v, 0), N_NODES - 1);
}

// ---------------- CSR build ----------------
__global__ void k_zero_cnt() {
    int i = blockIdx.x * blockDim.x + threadIdx.x;
    if (i < N_NODES) g_cnt[i] = 0;
}

__global__ void k_count(const int* __restrict__ dst, int E) {
    int e = blockIdx.x * blockDim.x + threadIdx.x;
    if (e < E) atomicAdd(&g_cnt[clamp_node(__ldg(dst + e))], 1);
}

__global__ void k_dinv() {
    int i = blockIdx.x * blockDim.x + threadIdx.x;
    if (i < N_NODES) g_dinv[i] = rsqrtf(1.0f + (float)g_cnt[i]);   // +1 self loop
}

// ---- scan phase 1: per-block exclusive scan (1024 elems/block) ------------
__global__ __launch_bounds__(1024) void k_scan1() {
    const int tid  = threadIdx.x;
    const int lane = tid & 31, wid = tid >> 5;
    int i = blockIdx.x * 1024 + tid;
    int v = (i < N_NODES) ? g_cnt[i] : 0;

    int x = v;                                         // warp inclusive scan
    #pragma unroll
    for (int o = 1; o < 32; o <<= 1) {
        int t = __shfl_up_sync(0xFFFFFFFFu, x, o);
        if (lane >= o) x += t;
    }
    __shared__ int wsum[32];
    if (lane == 31) wsum[wid] = x;
    __syncthreads();
    if (wid == 0) {                                    // scan the 32 warp sums
        int w = wsum[lane];
        #pragma unroll
        for (int o = 1; o < 32; o <<= 1) {
            int t = __shfl_up_sync(0xFFFFFFFFu, w, o);
            if (lane >= o) w += t;
        }
        wsum[lane] = w;
    }
    __syncthreads();
    int excl = x - v + (wid ? wsum[wid - 1] : 0);      // block-local exclusive
    if (i < N_NODES) g_cur[i] = excl;
    if (tid == 1023) g_bsum[blockIdx.x] = excl + v;    // block total
}

// ---- scan phase 2: inclusive scan of block totals (<=64) ------------------
__global__ void k_scan2() {
    __shared__ int s[64];
    int tid = threadIdx.x;                             // 64 threads
    s[tid] = (tid < SCAN_NB) ? g_bsum[tid] : 0;
    __syncthreads();
    #pragma unroll
    for (int o = 1; o < 64; o <<= 1) {                 // inclusive Hillis-Steele
        int t = (tid >= o) ? s[tid - o] : 0;
        __syncthreads();
        s[tid] += t;
        __syncthreads();
    }
    if (tid < SCAN_NB) g_bsum[tid] = s[tid];           // inclusive totals
}

// ---- scan phase 3: add preceding blocks' total ----------------------------
__global__ __launch_bounds__(1024) void k_scan3() {
    int i = blockIdx.x * 1024 + threadIdx.x;
    if (i < N_NODES && blockIdx.x > 0) g_cur[i] += g_bsum[blockIdx.x - 1];
}

// bucket fill: g_edge[pos] = {src, dinv[s]*dinv[d]}; g_cur advances to end
__global__ void k_fill(const int* __restrict__ src, const int* __restrict__ dst, int E) {
    int e = blockIdx.x * blockDim.x + threadIdx.x;
    if (e >= E) return;
    int s = clamp_node(__ldg(src + e));
    int d = clamp_node(__ldg(dst + e));
    float nrm = g_dinv[s] * g_dinv[d];
    int pos = atomicAdd(&g_cur[d], 1);
    g_edge[pos] = make_int2(s, __float_as_int(nrm));
}

// ---------------- layer-1 gather: AGGX = Â·x (split lo=d_out / g_hi) -------
__global__ __launch_bounds__(256) void k_gather1(const float* __restrict__ x,
                                                 float* __restrict__ lo) {
    int node = blockIdx.x * 8 + (threadIdx.x >> 5);
    int lane = threadIdx.x & 31;
    if (node >= N_NODES) return;
    float di = g_dinv[node];
    float4 acc = *(const float4*)(x + (size_t)node * 128 + lane * 4);
    float nn = di * di;
    acc.x *= nn; acc.y *= nn; acc.z *= nn; acc.w *= nn;

    int end = g_cur[node];            // after fill: end of bucket
    int beg = end - g_cnt[node];

    if (beg < end) {
        int2 e = __ldg(&g_edge[beg]);
        float4 v = *(const float4*)(x + (size_t)e.x * 128 + lane * 4);
        for (int j = beg; j < end; j++) {
            float nrm = __int_as_float(e.y);
            float4 cv = v;
            if (j + 1 < end) {                     // prefetch next edge
                e = __ldg(&g_edge[j + 1]);
                v = *(const float4*)(x + (size_t)e.x * 128 + lane * 4);
            }
            acc.x = fmaf(cv.x, nrm, acc.x);
            acc.y = fmaf(cv.y, nrm, acc.y);
            acc.z = fmaf(cv.z, nrm, acc.z);
            acc.w = fmaf(cv.w, nrm, acc.w);
        }
    }
    float* p = (lane < 16) ? (lo + (size_t)node * 64 + lane * 4)
                           : (g_hi + (size_t)node * 64 + (lane - 16) * 4);
    *(float4*)p = acc;
}

// ---------------- P = relu(AGGX @ W1 + b1), in place over split ------------
__global__ __launch_bounds__(256) void k_gemm1(const float* __restrict__ W1,
                                               const float* __restrict__ b1,
                                               float* __restrict__ lo) {
    __shared__ float sX[32][128];      // 16 KB
    __shared__ float sW[128 * 64];     // 32 KB
    const int tid = threadIdx.x;
    const int row0 = blockIdx.x * 32;

    for (int i = tid; i < 32 * 32; i += 256) {
        int r = i >> 5, c = i & 31;
        int row = row0 + r;
        float4 v = make_float4(0.f, 0.f, 0.f, 0.f);
        if (row < N_NODES)
            v = (c < 16) ? *(const float4*)(lo + (size_t)row * 64 + c * 4)
                         : *(const float4*)(g_hi + (size_t)row * 64 + (c - 16) * 4);
        *(float4*)(&sX[r][c * 4]) = v;
    }

    const int warp = tid >> 5, lane = tid & 31;
    float accA[4][2] = {}, accB[4][2] = {};

    #pragma unroll
    for (int half = 0; half < 2; half++) {
        __syncthreads();
        for (int i = tid; i < 128 * 16; i += 256) {    // W half [128 x 64]
            int k = i >> 4, c4 = i & 15;
            ((float4*)sW)[i] = *(const float4*)(W1 + (size_t)k * 128 + half * 64 + c4 * 4);
        }
        __syncthreads();
        #pragma unroll 4
        for (int k = 0; k < 128; k++) {
            float2 wv = *(const float2*)(sW + k * 64 + lane * 2);
            #pragma unroll
            for (int r = 0; r < 4; r++) {
                float xv = sX[warp * 4 + r][k];
                if (half == 0) {
                    accA[r][0] = fmaf(xv, wv.x, accA[r][0]);
                    accA[r][1] = fmaf(xv, wv.y, accA[r][1]);
                } else {
                    accB[r][0] = fmaf(xv, wv.x, accB[r][0]);
                    accB[r][1] = fmaf(xv, wv.y, accB[r][1]);
                }
            }
        }
    }

    float2 bA = *(const float2*)(b1 + lane * 2);
    float2 bB = *(const float2*)(b1 + 64 + lane * 2);
    #pragma unroll
    for (int r = 0; r < 4; r++) {
        int row = row0 + warp * 4 + r;
        if (row < N_NODES) {
            float2 oA = make_float2(fmaxf(accA[r][0] + bA.x, 0.f),
                                    fmaxf(accA[r][1] + bA.y, 0.f));
            float2 oB = make_float2(fmaxf(accB[r][0] + bB.x, 0.f),
                                    fmaxf(accB[r][1] + bB.y, 0.f));
            *(float2*)(lo   + (size_t)row * 64 + lane * 2) = oA;
            *(float2*)(g_hi + (size_t)row * 64 + lane * 2) = oB;
        }
    }
}

// ---------------- Q = P @ W2, in place into g_hi ---------------------------
__global__ __launch_bounds__(256) void k_gemm2(const float* __restrict__ W2,
                                               const float* __restrict__ lo) {
    __shared__ float sX[32][128];      // 16 KB
    __shared__ float sW[128 * 64];     // 32 KB
    const int tid = threadIdx.x;
    const int row0 = blockIdx.x * 32;

    for (int i = tid; i < 32 * 32; i += 256) {
        int r = i >> 5, c = i & 31;
        int row = row0 + r;
        float4 v = make_float4(0.f, 0.f, 0.f, 0.f);
        if (row < N_NODES)
            v = (c < 16) ? *(const float4*)(lo + (size_t)row * 64 + c * 4)
                         : *(const float4*)(g_hi + (size_t)row * 64 + (c - 16) * 4);
        *(float4*)(&sX[r][c * 4]) = v;
    }
    for (int i = tid; i < 128 * 16; i += 256) {        // W2 [128 x 64]
        int k = i >> 4, c4 = i & 15;
        ((float4*)sW)[i] = *(const float4*)(W2 + (size_t)k * 64 + c4 * 4);
    }
    __syncthreads();

    const int warp = tid >> 5, lane = tid & 31;
    float acc[4][2] = {};
    #pragma unroll 4
    for (int k = 0; k < 128; k++) {
        float2 wv = *(const float2*)(sW + k * 64 + lane * 2);
        #pragma unroll
        for (int r = 0; r < 4; r++) {
            float xv = sX[warp * 4 + r][k];
            acc[r][0] = fmaf(xv, wv.x, acc[r][0]);
            acc[r][1] = fmaf(xv, wv.y, acc[r][1]);
        }
    }
    #pragma unroll
    for (int r = 0; r < 4; r++) {
        int row = row0 + warp * 4 + r;
        if (row < N_NODES)
            *(float2*)(g_hi + (size_t)row * 64 + lane * 2)
                = make_float2(acc[r][0], acc[r][1]);
    }
}

// ---------------- layer-2 gather + bias + log_softmax, fused ---------------
__global__ __launch_bounds__(256) void k_gather2_lsm(const float* __restrict__ b2,
                                                     float* __restrict__ out) {
    int node = blockIdx.x * 8 + (threadIdx.x >> 5);
    int lane = threadIdx.x & 31;
    if (node >= N_NODES) return;
    float di = g_dinv[node];
    float2 acc = *(const float2*)(g_hi + (size_t)node * 64 + lane * 2);
    float nn = di * di;
    acc.x *= nn; acc.y *= nn;

    int end = g_cur[node];
    int beg = end - g_cnt[node];

    if (beg < end) {
        int2 e = __ldg(&g_edge[beg]);
        float2 v = *(const float2*)(g_hi + (size_t)e.x * 64 + lane * 2);
        for (int j = beg; j < end; j++) {
            float nrm = __int_as_float(e.y);
            float2 cv = v;
            if (j + 1 < end) {                     // prefetch next edge
                e = __ldg(&g_edge[j + 1]);
                v = *(const float2*)(g_hi + (size_t)e.x * 64 + lane * 2);
            }
            acc.x = fmaf(cv.x, nrm, acc.x);
            acc.y = fmaf(cv.y, nrm, acc.y);
        }
    }

    float2 bb = *(const float2*)(b2 + lane * 2);
    acc.x += bb.x; acc.y += bb.y;
    float m = fmaxf(acc.x, acc.y);
    #pragma unroll
    for (int o = 16; o; o >>= 1) m = fmaxf(m, __shfl_xor_sync(0xFFFFFFFFu, m, o));
    float s = __expf(acc.x - m) + __expf(acc.y - m);
    #pragma unroll
    for (int o = 16; o; o >>= 1) s += __shfl_xor_sync(0xFFFFFFFFu, s, o);
    float l = m + __logf(s);
    *(float2*)(out + (size_t)node * 64 + lane * 2)
        = make_float2(acc.x - l, acc.y - l);
}

// ---------------- launch ----------------
extern "C" void kernel_launch(void* const* d_in, const int* in_sizes, int n_in,
                              void* d_out, int out_size) {
    const float* x  = (const float*)d_in[0];
    const int*   ei = (const int*)d_in[1];        // int64 ref -> int32 delivered
    const float* W1 = (const float*)d_in[2];
    const float* b1 = (const float*)d_in[3];
    const float* W2 = (const float*)d_in[4];
    const float* b2 = (const float*)d_in[5];
    float* out = (float*)d_out;

    const int E = in_sizes[1] / 2;
    const int* src = ei;
    const int* dst = ei + E;

    const int TB = 256;
    const int nbN = (N_NODES + TB - 1) / TB;
    const int nbE = (E + TB - 1) / TB;
    const int nbW = (N_NODES + 7) / 8;            // warp-per-node kernels

    // 1) CSR build: count, dinv, 3-phase scan, fill
    k_zero_cnt<<<nbN, TB>>>();
    k_count   <<<nbE, TB>>>(dst, E);
    k_dinv    <<<nbN, TB>>>();
    k_scan1   <<<SCAN_NB, 1024>>>();
    k_scan2   <<<1, 64>>>();
    k_scan3   <<<SCAN_NB, 1024>>>();
    k_fill    <<<nbE, TB>>>(src, dst, E);

    // 2) AGGX = Â·x   (gather; split lo=d_out cols 0..63, g_hi cols 64..127)
    k_gather1<<<nbW, TB>>>(x, out);

    // 3) P = relu(AGGX @ W1 + b1)   in place over split storage
    k_gemm1<<<(N_NODES + 31) / 32, TB>>>(W1, b1, out);

    // 4) Q = P @ W2   -> g_hi
    k_gemm2<<<(N_NODES + 31) / 32, TB>>>(W2, out);

    // 5+6) d_out = log_softmax(Â·Q + b2)   (fused gather + bias + softmax)
    k_gather2_lsm<<<nbW, TB>>>(b2, out);
}

// round 13
// speedup vs baseline: 1.3401x; 1.0003x over previous
#include <cuda_runtime.h>
#include <cuda_bf16.h>
#include <math.h>

#define N_NODES 50000
#define D_IN    128
#define D_HID   128
#define D_OUT   64
#define SCAN_NB ((N_NODES + 1023) / 1024)    // 49 blocks

typedef unsigned long long u64;

// ---------------- device scratch (~19.8 MB) ----------------
__device__ float g_dinv[N_NODES];            // deg^{-1/2}
__device__ int   g_cnt [N_NODES];            // in-degree (edges only)
__device__ int   g_cur [N_NODES];            // scan result -> fill cursor -> end ptr
__device__ int   g_bsum[64];                 // per-block scan totals
__device__ int2  g_edge[800000];             // CSR payload: {src, norm bits}
__device__ float g_hi  [N_NODES * 64];       // hi half of layer-1 agg / Q

__device__ __forceinline__ int clamp_node(int v) {
    return min(max(v, 0), N_NODES - 1);
}

// packed fp32x2 FMA: acc = a*b + acc  (per-half independent fp32 fma)
#define FMA2(acc, a, b) \
    asm("fma.rn.f32x2 %0, %1, %2, %3;" : "=l"(acc) : "l"(a), "l"(b), "l"(acc))

__device__ __forceinline__ float unpack_sum(u64 v) {
    float lo, hi;
    asm("mov.b64 {%0,%1}, %2;" : "=f"(lo), "=f"(hi) : "l"(v));
    return lo + hi;
}

__device__ __forceinline__ u64 pack2(float a, float b) {
    u64 r;
    asm("mov.b64 %0, {%1,%2};" : "=l"(r) : "f"(a), "f"(b));
    return r;
}

// ---------------- CSR build ----------------
__global__ void k_zero_cnt() {
    int i = blockIdx.x * blockDim.x + threadIdx.x;
    if (i < N_NODES) g_cnt[i] = 0;
}

__global__ void k_count(const int* __restrict__ dst, int E) {
    int e = blockIdx.x * blockDim.x + threadIdx.x;
    if (e < E) atomicAdd(&g_cnt[clamp_node(__ldg(dst + e))], 1);
}

// ---- scan phase 1 (+ fused dinv): per-block exclusive scan ----------------
__global__ __launch_bounds__(1024) void k_scan1() {
    const int tid  = threadIdx.x;
    const int lane = tid & 31, wid = tid >> 5;
    int i = blockIdx.x * 1024 + tid;
    int v = (i < N_NODES) ? g_cnt[i] : 0;
    if (i < N_NODES) g_dinv[i] = rsqrtf(1.0f + (float)v);   // +1 self loop

    int x = v;                                         // warp inclusive scan
    #pragma unroll
    for (int o = 1; o < 32; o <<= 1) {
        int t = __shfl_up_sync(0xFFFFFFFFu, x, o);
        if (lane >= o) x += t;
    }
    __shared__ int wsum[32];
    if (lane == 31) wsum[wid] = x;
    __syncthreads();
    if (wid == 0) {                                    // scan the 32 warp sums
        int w = wsum[lane];
        #pragma unroll
        for (int o = 1; o < 32; o <<= 1) {
            int t = __shfl_up_sync(0xFFFFFFFFu, w, o);
            if (lane >= o) w += t;
        }
        wsum[lane] = w;
    }
    __syncthreads();
    int excl = x - v + (wid ? wsum[wid - 1] : 0);      // block-local exclusive
    if (i < N_NODES) g_cur[i] = excl;
    if (tid == 1023) g_bsum[blockIdx.x] = excl + v;    // block total
}

// ---- scan phase 2: inclusive scan of block totals (<=64) ------------------
__global__ void k_scan2() {
    __shared__ int s[64];
    int tid = threadIdx.x;                             // 64 threads
    s[tid] = (tid < SCAN_NB) ? g_bsum[tid] : 0;
    __syncthreads();
    #pragma unroll
    for (int o = 1; o < 64; o <<= 1) {                 // inclusive Hillis-Steele
        int t = (tid >= o) ? s[tid - o] : 0;
        __syncthreads();
        s[tid] += t;
        __syncthreads();
    }
    if (tid < SCAN_NB) g_bsum[tid] = s[tid];           // inclusive totals
}

// ---- scan phase 3: add preceding blocks' total ----------------------------
__global__ __launch_bounds__(1024) void k_scan3() {
    int i = blockIdx.x * 1024 + threadIdx.x;
    if (i < N_NODES && blockIdx.x > 0) g_cur[i] += g_bsum[blockIdx.x - 1];
}

// bucket fill: g_edge[pos] = {src, dinv[s]*dinv[d]}; g_cur advances to end
__global__ void k_fill(const int* __restrict__ src, const int* __restrict__ dst, int E) {
    int e = blockIdx.x * blockDim.x + threadIdx.x;
    if (e >= E) return;
    int s = clamp_node(__ldg(src + e));
    int d = clamp_node(__ldg(dst + e));
    float nrm = g_dinv[s] * g_dinv[d];
    int pos = atomicAdd(&g_cur[d], 1);
    g_edge[pos] = make_int2(s, __float_as_int(nrm));
}

// ---------------- layer-1 gather: AGGX = Â·x (split lo=d_out / g_hi) -------
__global__ __launch_bounds__(256) void k_gather1(const float* __restrict__ x,
                                                 float* __restrict__ lo) {
    int node = blockIdx.x * 8 + (threadIdx.x >> 5);
    int lane = threadIdx.x & 31;
    if (node >= N_NODES) return;
    float di = g_dinv[node];
    float4 acc = *(const float4*)(x + (size_t)node * 128 + lane * 4);
    float nn = di * di;
    acc.x *= nn; acc.y *= nn; acc.z *= nn; acc.w *= nn;

    int end = g_cur[node];            // after fill: end of bucket
    int beg = end - g_cnt[node];

    if (beg < end) {
        int2 e = __ldg(&g_edge[beg]);
        float4 v = *(const float4*)(x + (size_t)e.x * 128 + lane * 4);
        for (int j = beg; j < end; j++) {
            float nrm = __int_as_float(e.y);
            float4 cv = v;
            if (j + 1 < end) {                     // prefetch next edge
                e = __ldg(&g_edge[j + 1]);
                v = *(const float4*)(x + (size_t)e.x * 128 + lane * 4);
            }
            acc.x = fmaf(cv.x, nrm, acc.x);
            acc.y = fmaf(cv.y, nrm, acc.y);
            acc.z = fmaf(cv.z, nrm, acc.z);
            acc.w = fmaf(cv.w, nrm, acc.w);
        }
    }
    float* p = (lane < 16) ? (lo + (size_t)node * 64 + lane * 4)
                           : (g_hi + (size_t)node * 64 + (lane - 16) * 4);
    *(float4*)p = acc;
}

// ---------------- P = relu(AGGX @ W1 + b1), in place, packed-f32x2 ---------
// Split-K packing: acc u64 = {sum over even k, sum over odd k}.
// sWpk[kp][c] = {W[2kp][c], W[2kp+1][c]}. Lane owns cols {lane, lane+32}.
__global__ __launch_bounds__(256) void k_gemm1(const float* __restrict__ W1,
                                               const float* __restrict__ b1,
                                               float* __restrict__ lo) {
    __shared__ float sX[32][128];      // 16 KB (k contiguous per row)
    __shared__ u64   sWpk[64][64];     // 32 KB
    const int tid = threadIdx.x;
    const int row0 = blockIdx.x * 32;

    // stage X tile from split storage (full stage before in-place overwrite)
    for (int i = tid; i < 32 * 32; i += 256) {
        int r = i >> 5, c = i & 31;
        int row = row0 + r;
        float4 v = make_float4(0.f, 0.f, 0.f, 0.f);
        if (row < N_NODES)
            v = (c < 16) ? *(const float4*)(lo + (size_t)row * 64 + c * 4)
                         : *(const float4*)(g_hi + (size_t)row * 64 + (c - 16) * 4);
        *(float4*)(&sX[r][c * 4]) = v;
    }

    const int warp = tid >> 5, lane = tid & 31;

    #pragma unroll
    for (int half = 0; half < 2; half++) {
        __syncthreads();
        // pack W half [128k x 64c] into k-pair u64 tile
        for (int i = tid; i < 64 * 64; i += 256) {
            int kp = i >> 6, c = i & 63;
            float w0 = W1[(size_t)(2 * kp)     * 128 + half * 64 + c];
            float w1 = W1[(size_t)(2 * kp + 1) * 128 + half * 64 + c];
            sWpk[kp][c] = pack2(w0, w1);
        }
        __syncthreads();

        u64 acc[4][2];
        #pragma unroll
        for (int r = 0; r < 4; r++) { acc[r][0] = 0ull; acc[r][1] = 0ull; }

        #pragma unroll 4
        for (int kp = 0; kp < 64; kp++) {
            u64 b0 = sWpk[kp][lane];
            u64 b1v = sWpk[kp][lane + 32];
            #pragma unroll
            for (int r = 0; r < 4; r++) {
                u64 a = *(const u64*)&sX[warp * 4 + r][kp * 2];   // broadcast
                FMA2(acc[r][0], a, b0);
                FMA2(acc[r][1], a, b1v);
            }
        }

        float bc0 = b1[half * 64 + lane];
        float bc1 = b1[half * 64 + lane + 32];
        #pragma unroll
        for (int r = 0; r < 4; r++) {
            int row = row0 + warp * 4 + r;
            if (row < N_NODES) {
                float r0 = fmaxf(unpack_sum(acc[r][0]) + bc0, 0.f);
                float r1 = fmaxf(unpack_sum(acc[r][1]) + bc1, 0.f);
                float* base = half ? g_hi : lo;
                base[(size_t)row * 64 + lane]      = r0;
                base[(size_t)row * 64 + lane + 32] = r1;
            }
        }
    }
}

// ---------------- Q = P @ W2, in place into g_hi, packed-f32x2 -------------
__global__ __launch_bounds__(256) void k_gemm2(const float* __restrict__ W2,
                                               const float* __restrict__ lo) {
    __shared__ float sX[32][128];      // 16 KB
    __shared__ u64   sWpk[64][64];     // 32 KB
    const int tid = threadIdx.x;
    const int row0 = blockIdx.x * 32;

    for (int i = tid; i < 32 * 32; i += 256) {
        int r = i >> 5, c = i & 31;
        int row = row0 + r;
        float4 v = make_float4(0.f, 0.f, 0.f, 0.f);
        if (row < N_NODES)
            v = (c < 16) ? *(const float4*)(lo + (size_t)row * 64 + c * 4)
                         : *(const float4*)(g_hi + (size_t)row * 64 + (c - 16) * 4);
        *(float4*)(&sX[r][c * 4]) = v;
    }
    for (int i = tid; i < 64 * 64; i += 256) {         // pack W2 [128 x 64]
        int kp = i >> 6, c = i & 63;
        float w0 = W2[(size_t)(2 * kp)     * 64 + c];
        float w1 = W2[(size_t)(2 * kp + 1) * 64 + c];
        sWpk[kp][c] = pack2(w0, w1);
    }
    __syncthreads();

    const int warp = tid >> 5, lane = tid & 31;
    u64 acc[4][2];
    #pragma unroll
    for (int r = 0; r < 4; r++) { acc[r][0] = 0ull; acc[r][1] = 0ull; }

    #pragma unroll 4
    for (int kp = 0; kp < 64; kp++) {
        u64 b0 = sWpk[kp][lane];
        u64 b1v = sWpk[kp][lane + 32];
        #pragma unroll
        for (int r = 0; r < 4; r++) {
            u64 a = *(const u64*)&sX[warp * 4 + r][kp * 2];
            FMA2(acc[r][0], a, b0);
            FMA2(acc[r][1], a, b1v);
        }
    }
    #pragma unroll
    for (int r = 0; r < 4; r++) {
        int row = row0 + warp * 4 + r;
        if (row < N_NODES) {
            g_hi[(size_t)row * 64 + lane]      = unpack_sum(acc[r][0]);
            g_hi[(size_t)row * 64 + lane + 32] = unpack_sum(acc[r][1]);
        }
    }
}

// ---------------- layer-2 gather + bias + log_softmax, fused ---------------
__global__ __launch_bounds__(256) void k_gather2_lsm(const float* __restrict__ b2,
                                                     float* __restrict__ out) {
    int node = blockIdx.x * 8 + (threadIdx.x >> 5);
    int lane = threadIdx.x & 31;
    if (node >= N_NODES) return;
    float di = g_dinv[node];
    float2 acc = *(const float2*)(g_hi + (size_t)node * 64 + lane * 2);
    float nn = di * di;
    acc.x *= nn; acc.y *= nn;

    int end = g_cur[node];
    int beg = end - g_cnt[node];

    if (beg < end) {
        int2 e = __ldg(&g_edge[beg]);
        float2 v = *(const float2*)(g_hi + (size_t)e.x * 64 + lane * 2);
        for (int j = beg; j < end; j++) {
            float nrm = __int_as_float(e.y);
            float2 cv = v;
            if (j + 1 < end) {                     // prefetch next edge
                e = __ldg(&g_edge[j + 1]);
                v = *(const float2*)(g_hi + (size_t)e.x * 64 + lane * 2);
            }
            acc.x = fmaf(cv.x, nrm, acc.x);
            acc.y = fmaf(cv.y, nrm, acc.y);
        }
    }

    float2 bb = *(const float2*)(b2 + lane * 2);
    acc.x += bb.x; acc.y += bb.y;
    float m = fmaxf(acc.x, acc.y);
    #pragma unroll
    for (int o = 16; o; o >>= 1) m = fmaxf(m, __shfl_xor_sync(0xFFFFFFFFu, m, o));
    float s = __expf(acc.x - m) + __expf(acc.y - m);
    #pragma unroll
    for (int o = 16; o; o >>= 1) s += __shfl_xor_sync(0xFFFFFFFFu, s, o);
    float l = m + __logf(s);
    *(float2*)(out + (size_t)node * 64 + lane * 2)
        = make_float2(acc.x - l, acc.y - l);
}

// ---------------- launch ----------------
extern "C" void kernel_launch(void* const* d_in, const int* in_sizes, int n_in,
                              void* d_out, int out_size) {
    const float* x  = (const float*)d_in[0];
    const int*   ei = (const int*)d_in[1];        // int64 ref -> int32 delivered
    const float* W1 = (const float*)d_in[2];
    const float* b1 = (const float*)d_in[3];
    const float* W2 = (const float*)d_in[4];
    const float* b2 = (const float*)d_in[5];
    float* out = (float*)d_out;

    const int E = in_sizes[1] / 2;
    const int* src = ei;
    const int* dst = ei + E;

    const int TB = 256;
    const int nbN = (N_NODES + TB - 1) / TB;
    const int nbE = (E + TB - 1) / TB;
    const int nbW = (N_NODES + 7) / 8;            // warp-per-node kernels

    // 1) CSR build: count, scan(+dinv), fill
    k_zero_cnt<<<nbN, TB>>>();
    k_count   <<<nbE, TB>>>(dst, E);
    k_scan1   <<<SCAN_NB, 1024>>>();
    k_scan2   <<<1, 64>>>();
    k_scan3   <<<SCAN_NB, 1024>>>();
    k_fill    <<<nbE, TB>>>(src, dst, E);

    // 2) AGGX = Â·x   (gather; split lo=d_out cols 0..63, g_hi cols 64..127)
    k_gather1<<<nbW, TB>>>(x, out);

    // 3) P = relu(AGGX @ W1 + b1)   in place over split storage
    k_gemm1<<<(N_NODES + 31) / 32, TB>>>(W1, b1, out);

    // 4) Q = P @ W2   -> g_hi
    k_gemm2<<<(N_NODES + 31) / 32, TB>>>(W2, out);

    // 5+6) d_out = log_softmax(Â·Q + b2)   (fused gather + bias + softmax)
    k_gather2_lsm<<<nbW, TB>>>(b2, out);
}